// round 1
// baseline (speedup 1.0000x reference)
#include <cuda_runtime.h>

// SCNN 4-direction message passing.
// y[b,c,h,w]; vertical passes scan H with conv along W (L=256, stride_l=1),
// horizontal passes scan W with conv along H (L=128, stride_l=W).
// Each step: y_cur = y_cur + relu( sum_{ci,k} w[co,ci,k] * y_prev[ci, l+k-4] )

#define C_   128
#define H_   128
#define W_   256
#define B_   8
#define KS   9
#define PAD  4

#define TCO  32          // co tile per block
#define TL   32          // l tile per block
#define NTH  128         // threads per block
#define CI_CHUNK 16
#define WROW (CI_CHUNK*KS + 1)   // 145, padded: co-stride 145 % 32 = 17 -> no bank conflicts

__global__ __launch_bounds__(NTH) void scnn_step(
    float* __restrict__ y, const float* __restrict__ w,
    int base_cur, int base_prev, int stride_l, int L)
{
    __shared__ float ps[C_][TL + 2*PAD];     // prev row tile, all ci: 128*40*4 = 20.5 KB
    __shared__ float ws[TCO * WROW];         // weight chunk: 32*145*4 = 18.6 KB

    const int b   = blockIdx.z;
    const int co0 = blockIdx.y * TCO;
    const int l0  = blockIdx.x * TL;
    const int tid = threadIdx.x;

    const int strideC = H_ * W_;
    const int bbase   = b * (C_ * strideC);

    // ---- stage prev row tile (with zero-padded halo) ----
    const float* yprev = y + bbase + base_prev;
    #pragma unroll 1
    for (int idx = tid; idx < C_ * (TL + 2*PAD); idx += NTH) {
        int ci = idx / (TL + 2*PAD);
        int j  = idx % (TL + 2*PAD);
        int gl = l0 + j - PAD;
        float v = 0.0f;
        if (gl >= 0 && gl < L) v = yprev[ci * strideC + gl * stride_l];
        ps[ci][j] = v;
    }

    // thread micro-tile: 2 co x 4 l
    const int lg   = tid & 7;       // 0..7  -> l group
    const int cog  = tid >> 3;      // 0..15 -> co group
    const int lloc = lg * 4;
    const int coA  = cog * 2;

    float acc[2][4];
    #pragma unroll
    for (int i = 0; i < 2; i++)
        #pragma unroll
        for (int j = 0; j < 4; j++) acc[i][j] = 0.0f;

    #pragma unroll 1
    for (int cb = 0; cb < C_; cb += CI_CHUNK) {
        __syncthreads();
        // stage weight chunk: [TCO][CI_CHUNK][KS] -> ws[co*WROW + ci*KS + k]
        const float* wg = w + (long)co0 * (C_ * KS) + cb * KS;
        #pragma unroll 1
        for (int idx = tid; idx < TCO * CI_CHUNK * KS; idx += NTH) {
            int co  = idx / (CI_CHUNK * KS);
            int rem = idx % (CI_CHUNK * KS);
            ws[co * WROW + rem] = wg[co * (C_ * KS) + rem];
        }
        __syncthreads();

        #pragma unroll 1
        for (int ci = 0; ci < CI_CHUNK; ci++) {
            // sliding window of prev values for this thread's 4 l-outputs
            float pv[4 + KS - 1];
            const float* psrow = &ps[cb + ci][lloc];
            #pragma unroll
            for (int i = 0; i < 4 + KS - 1; i++) pv[i] = psrow[i];

            const float* wr0 = &ws[(coA    ) * WROW + ci * KS];
            const float* wr1 = &ws[(coA + 1) * WROW + ci * KS];
            #pragma unroll
            for (int k = 0; k < KS; k++) {
                float w0 = wr0[k];
                float w1 = wr1[k];
                #pragma unroll
                for (int il = 0; il < 4; il++) {
                    acc[0][il] = fmaf(w0, pv[il + k], acc[0][il]);
                    acc[1][il] = fmaf(w1, pv[il + k], acc[1][il]);
                }
            }
        }
    }

    // ---- y_cur += relu(conv) ----
    #pragma unroll
    for (int i = 0; i < 2; i++) {
        int co = co0 + coA + i;
        float* yo = y + bbase + co * strideC + base_cur;
        #pragma unroll
        for (int il = 0; il < 4; il++) {
            int l   = l0 + lloc + il;
            float r = acc[i][il];
            r = r > 0.0f ? r : 0.0f;
            yo[l * stride_l] += r;
        }
    }
}

extern "C" void kernel_launch(void* const* d_in, const int* in_sizes, int n_in,
                              void* d_out, int out_size)
{
    const float* x    = (const float*)d_in[0];
    const float* w_ud = (const float*)d_in[1];
    const float* w_du = (const float*)d_in[2];
    const float* w_lr = (const float*)d_in[3];
    const float* w_rl = (const float*)d_in[4];
    float* y = (float*)d_out;

    // in-place scan: start from a copy of x
    cudaMemcpyAsync(y, x, (size_t)out_size * sizeof(float),
                    cudaMemcpyDeviceToDevice);

    dim3 gridV(W_ / TL, C_ / TCO, B_);   // (8,4,8) = 256 blocks/step
    dim3 gridH(H_ / TL, C_ / TCO, B_);   // (4,4,8) = 128 blocks/step

    // pass 1: up->down (scan H forward, conv along W)
    for (int h = 1; h < H_; h++)
        scnn_step<<<gridV, NTH>>>(y, w_ud, h * W_, (h - 1) * W_, 1, W_);
    // pass 2: down->up
    for (int h = H_ - 2; h >= 0; h--)
        scnn_step<<<gridV, NTH>>>(y, w_du, h * W_, (h + 1) * W_, 1, W_);
    // pass 3: left->right (scan W forward, conv along H)
    for (int wi = 1; wi < W_; wi++)
        scnn_step<<<gridH, NTH>>>(y, w_lr, wi, wi - 1, W_, H_);
    // pass 4: right->left
    for (int wi = W_ - 2; wi >= 0; wi--)
        scnn_step<<<gridH, NTH>>>(y, w_rl, wi, wi + 1, W_, H_);
}

// round 2
// speedup vs baseline: 2.1352x; 2.1352x over previous
#include <cuda_runtime.h>

#define C_   128
#define H_   128
#define W_   256
#define B_   8
#define KS   9
#define PAD  4
#define NTH  128
#define TCO  32
#define CI_CHUNK 32
#define WS_STRIDE (CI_CHUNK*12 + 4)   // 388 floats; 388%32=4 -> conflict-free co rows
#define STRIDE_C (H_*W_)              // 32768, same for y and yt

// scratch: transposed tensor + padded weights (device globals, no allocation)
__device__ float g_yt[(size_t)B_ * C_ * H_ * W_];          // 128 MB
__device__ float g_wpad[4 * C_ * C_ * 12];                  // 3 MB

// ---------------- weight padding: w[co][ci][9] -> wpad[p][co][ci][12] ----------------
__global__ void pad_weights(const float* __restrict__ w0, const float* __restrict__ w1,
                            const float* __restrict__ w2, const float* __restrict__ w3)
{
    int row = blockIdx.x * blockDim.x + threadIdx.x;   // (p, co, ci)
    if (row >= 4 * C_ * C_) return;
    int p  = row / (C_ * C_);
    int rc = row % (C_ * C_);
    const float* src = (p == 0 ? w0 : p == 1 ? w1 : p == 2 ? w2 : w3) + rc * KS;
    float* dst = g_wpad + (size_t)row * 12;
    #pragma unroll
    for (int k = 0; k < 9; k++) dst[k] = src[k];
    dst[9] = 0.f; dst[10] = 0.f; dst[11] = 0.f;
}

// ---------------- 32x32 tiled transpose of [R x Ccols] planes ----------------
__global__ void transpose_planes(const float* __restrict__ src, float* __restrict__ dst,
                                 int R, int Ccols)
{
    __shared__ float t[32][33];
    size_t plane = (size_t)blockIdx.z * R * Ccols;
    int x  = blockIdx.x * 32 + threadIdx.x;
    int y0 = blockIdx.y * 32 + threadIdx.y;
    #pragma unroll
    for (int j = 0; j < 32; j += 8)
        t[threadIdx.y + j][threadIdx.x] = src[plane + (size_t)(y0 + j) * Ccols + x];
    __syncthreads();
    int xo = blockIdx.y * 32 + threadIdx.x;
    int yo = blockIdx.x * 32 + threadIdx.y;
    #pragma unroll
    for (int j = 0; j < 32; j += 8)
        dst[plane + (size_t)(yo + j) * R + xo] = t[threadIdx.x][threadIdx.y + j];
}

// ---------------- one scan step: y[cur] += relu(conv1d(y[prev])) ----------------
// l is contiguous (stride 1). TL: l-tile, UL: l per thread. micro-tile = 2co x UL.
template<int TL, int UL>
__global__ __launch_bounds__(NTH) void scnn_step(
    float* __restrict__ y, const float* __restrict__ wp,
    int base_cur, int base_prev, int L)
{
    extern __shared__ float smem[];
    float* ps = smem;                        // [C_][TL+8]
    float* ws = smem + C_ * (TL + 8);        // [TCO][WS_STRIDE]

    const int b   = blockIdx.z;
    const int co0 = blockIdx.y * TCO;
    const int l0  = blockIdx.x * TL;
    const int tid = threadIdx.x;
    const size_t bbase = (size_t)b * C_ * STRIDE_C;

    // stage prev row tile (zero-padded halo), contiguous loads
    {
        const float* yprev = y + bbase + base_prev;
        const int rowlen = TL + 8;
        #pragma unroll 1
        for (int idx = tid; idx < C_ * rowlen; idx += NTH) {
            int ci = idx / rowlen;
            int j  = idx % rowlen;
            int gl = l0 + j - PAD;
            float v = 0.0f;
            if (gl >= 0 && gl < L) v = yprev[(size_t)ci * STRIDE_C + gl];
            ps[idx] = v;
        }
    }

    // lane mapping: lg in [0,8) (l groups), cog in [0,16) (co pairs)
    const int lg   = tid & 7;
    const int cog  = tid >> 3;
    const int lloc = lg * UL;
    const int coA  = cog * 2;

    float acc[2][UL];
    #pragma unroll
    for (int i = 0; i < 2; i++)
        #pragma unroll
        for (int j = 0; j < UL; j++) acc[i][j] = 0.0f;

    #pragma unroll 1
    for (int cb = 0; cb < C_; cb += CI_CHUNK) {
        __syncthreads();
        // stage padded weight chunk via float4: wpad[co0+co][cb+ci][12]
        {
            const float4* src = (const float4*)(wp + ((size_t)co0 * C_ + cb) * 12);
            #pragma unroll 1
            for (int idx = tid; idx < TCO * (CI_CHUNK * 3); idx += NTH) {
                int co = idx / (CI_CHUNK * 3);
                int r  = idx % (CI_CHUNK * 3);
                *(float4*)&ws[co * WS_STRIDE + r * 4] = src[(size_t)co * (C_ * 3) + r];
            }
        }
        __syncthreads();

        #pragma unroll 1
        for (int ci = 0; ci < CI_CHUNK; ci++) {
            float pv[UL + 8];
            const float* psrow = &ps[(cb + ci) * (TL + 8) + lloc];
            if (UL == 4) {
                float4 p0 = *(const float4*)(psrow + 0);
                float4 p1 = *(const float4*)(psrow + 4);
                float4 p2 = *(const float4*)(psrow + 8);
                pv[0]=p0.x; pv[1]=p0.y; pv[2]=p0.z;  pv[3]=p0.w;
                pv[4]=p1.x; pv[5]=p1.y; pv[6]=p1.z;  pv[7]=p1.w;
                pv[8]=p2.x; pv[9]=p2.y; pv[10]=p2.z; pv[11]=p2.w;
            } else {
                #pragma unroll
                for (int i = 0; i < UL + 8; i += 2) {
                    float2 p = *(const float2*)(psrow + i);
                    pv[i] = p.x; pv[i + 1] = p.y;
                }
            }

            float wr[2][12];
            #pragma unroll
            for (int c = 0; c < 2; c++) {
                const float* wsr = &ws[(coA + c) * WS_STRIDE + ci * 12];
                float4 a = *(const float4*)(wsr + 0);
                float4 d = *(const float4*)(wsr + 4);
                float4 e = *(const float4*)(wsr + 8);
                wr[c][0]=a.x; wr[c][1]=a.y; wr[c][2]=a.z; wr[c][3]=a.w;
                wr[c][4]=d.x; wr[c][5]=d.y; wr[c][6]=d.z; wr[c][7]=d.w;
                wr[c][8]=e.x;
                (void)e;
            }

            #pragma unroll
            for (int k = 0; k < KS; k++)
                #pragma unroll
                for (int il = 0; il < UL; il++) {
                    acc[0][il] = fmaf(wr[0][k], pv[il + k], acc[0][il]);
                    acc[1][il] = fmaf(wr[1][k], pv[il + k], acc[1][il]);
                }
        }
    }

    // epilogue: vector RMW y_cur += relu(acc)
    #pragma unroll
    for (int i = 0; i < 2; i++) {
        float* yo = y + bbase + (size_t)(co0 + coA + i) * STRIDE_C + base_cur + l0 + lloc;
        if (UL == 4) {
            float4 o = *(float4*)yo;
            o.x += fmaxf(acc[i][0], 0.f);
            o.y += fmaxf(acc[i][1], 0.f);
            o.z += fmaxf(acc[i][2], 0.f);
            o.w += fmaxf(acc[i][3], 0.f);
            *(float4*)yo = o;
        } else {
            float2 o = *(float2*)yo;
            o.x += fmaxf(acc[i][0], 0.f);
            o.y += fmaxf(acc[i][1], 0.f);
            *(float2*)yo = o;
        }
    }
}

extern "C" void kernel_launch(void* const* d_in, const int* in_sizes, int n_in,
                              void* d_out, int out_size)
{
    const float* x    = (const float*)d_in[0];
    const float* w_ud = (const float*)d_in[1];
    const float* w_du = (const float*)d_in[2];
    const float* w_lr = (const float*)d_in[3];
    const float* w_rl = (const float*)d_in[4];
    float* y = (float*)d_out;

    float* yt;  cudaGetSymbolAddress((void**)&yt, g_yt);
    float* wp;  cudaGetSymbolAddress((void**)&wp, g_wpad);

    const int SMEM_V = (C_ * (32 + 8) + TCO * WS_STRIDE) * 4;   // 70144 B
    const int SMEM_H = (C_ * (16 + 8) + TCO * WS_STRIDE) * 4;   // 61952 B
    cudaFuncSetAttribute(scnn_step<32,4>, cudaFuncAttributeMaxDynamicSharedMemorySize, SMEM_V);
    cudaFuncSetAttribute(scnn_step<16,2>, cudaFuncAttributeMaxDynamicSharedMemorySize, SMEM_H);

    // prep: pad weights, copy x -> y
    pad_weights<<<(4 * C_ * C_ + 127) / 128, 128>>>(w_ud, w_du, w_lr, w_rl);
    cudaMemcpyAsync(y, x, (size_t)out_size * sizeof(float), cudaMemcpyDeviceToDevice);

    const int WOFF = C_ * C_ * 12;

    // vertical passes on y: scan H, conv along W (L=256)
    dim3 gridV(W_ / 32, C_ / TCO, B_);   // (8,4,8)
    for (int h = 1; h < H_; h++)
        scnn_step<32,4><<<gridV, NTH, SMEM_V>>>(y, wp + 0 * WOFF, h * W_, (h - 1) * W_, W_);
    for (int h = H_ - 2; h >= 0; h--)
        scnn_step<32,4><<<gridV, NTH, SMEM_V>>>(y, wp + 1 * WOFF, h * W_, (h + 1) * W_, W_);

    // transpose y[B,C,H,W] -> yt[B,C,W,H]
    {
        dim3 g(W_ / 32, H_ / 32, B_ * C_);
        transpose_planes<<<g, dim3(32, 8)>>>(y, yt, H_, W_);
    }

    // horizontal passes on yt: scan W, conv along H (contiguous, L=128)
    dim3 gridH(H_ / 16, C_ / TCO, B_);   // (8,4,8)
    for (int wi = 1; wi < W_; wi++)
        scnn_step<16,2><<<gridH, NTH, SMEM_H>>>(yt, wp + 2 * WOFF, wi * H_, (wi - 1) * H_, H_);
    for (int wi = W_ - 2; wi >= 0; wi--)
        scnn_step<16,2><<<gridH, NTH, SMEM_H>>>(yt, wp + 3 * WOFF, wi * H_, (wi + 1) * H_, H_);

    // transpose back yt[B,C,W,H] -> y[B,C,H,W]
    {
        dim3 g(H_ / 32, W_ / 32, B_ * C_);
        transpose_planes<<<g, dim3(32, 8)>>>(yt, y, W_, H_);
    }
}

// round 4
// speedup vs baseline: 2.2376x; 1.0480x over previous
#include <cuda_runtime.h>

#define C_   128
#define H_   128
#define W_   256
#define B_   8
#define KS   9
#define PAD  4
#define NTH  128
#define TCO  16                  // co per block (1 co per thread)
#define CI_CHUNK 32
#define WS_STRIDE (CI_CHUNK*12 + 4)     // 388 floats; 388%32=4 -> conflict-free co rows
#define WBUF (TCO * WS_STRIDE)          // 6208 floats per buffer
#define STRIDE_C (H_*W_)

// scratch: transposed tensor + padded weights (device globals, no allocation)
__device__ float g_yt[(size_t)B_ * C_ * H_ * W_];     // 128 MB
__device__ float g_wpad[4 * C_ * C_ * 12];            // 3 MB

// ---------------- weight padding: w[co][ci][9] -> wpad[p][co][ci][12] ----------------
__global__ void pad_weights(const float* __restrict__ w0, const float* __restrict__ w1,
                            const float* __restrict__ w2, const float* __restrict__ w3)
{
    int row = blockIdx.x * blockDim.x + threadIdx.x;   // (p, co, ci)
    if (row >= 4 * C_ * C_) return;
    int p  = row / (C_ * C_);
    int rc = row % (C_ * C_);
    const float* src = (p == 0 ? w0 : p == 1 ? w1 : p == 2 ? w2 : w3) + rc * KS;
    float* dst = g_wpad + (size_t)row * 12;
    #pragma unroll
    for (int k = 0; k < 9; k++) dst[k] = src[k];
    dst[9] = 0.f; dst[10] = 0.f; dst[11] = 0.f;
}

// ---------------- 32x32 tiled transpose of [R x Ccols] planes ----------------
__global__ void transpose_planes(const float* __restrict__ src, float* __restrict__ dst,
                                 int R, int Ccols)
{
    __shared__ float t[32][33];
    size_t plane = (size_t)blockIdx.z * R * Ccols;
    int x  = blockIdx.x * 32 + threadIdx.x;
    int y0 = blockIdx.y * 32 + threadIdx.y;
    #pragma unroll
    for (int j = 0; j < 32; j += 8)
        t[threadIdx.y + j][threadIdx.x] = src[plane + (size_t)(y0 + j) * Ccols + x];
    __syncthreads();
    int xo = blockIdx.y * 32 + threadIdx.x;
    int yo = blockIdx.x * 32 + threadIdx.y;
    #pragma unroll
    for (int j = 0; j < 32; j += 8)
        dst[plane + (size_t)(yo + j) * R + xo] = t[threadIdx.x][threadIdx.y + j];
}

// ---------------- one scan step: y[cur] += relu(conv1d(y[prev])) ----------------
// l contiguous (stride 1). TL=32 l-tile; micro-tile = 1 co x 4 l per thread.
// Weight chunks double-buffered: staging chunk cb+1 overlaps compute of chunk cb.
template<int TL>
__global__ __launch_bounds__(NTH) void scnn_step(
    float* __restrict__ y, const float* __restrict__ wp,
    int base_cur, int base_prev, int L)
{
    extern __shared__ float smem[];
    float* ps = smem;                 // [C_][TL+8]  (prev row, zero-padded halo)
    float* ws = smem + C_ * (TL + 8); // [2][TCO][WS_STRIDE]

    const int b   = blockIdx.z;
    const int co0 = blockIdx.y * TCO;
    const int l0  = blockIdx.x * TL;
    const int tid = threadIdx.x;
    const size_t bbase = (size_t)b * C_ * STRIDE_C;

    const float4* wsrc = (const float4*)(wp + (size_t)co0 * (C_ * 12));
    const int NCHUNK = C_ / CI_CHUNK;       // 4
    const int F4_PER_CHUNK = TCO * CI_CHUNK * 3;   // 1536 float4

    // ---- stage prev row tile (halo) + weight chunk 0 ----
    {
        const float* yprev = y + bbase + base_prev;
        const int rowlen = TL + 8;
        #pragma unroll 1
        for (int idx = tid; idx < C_ * rowlen; idx += NTH) {
            int ci = idx / rowlen;
            int j  = idx % rowlen;
            int gl = l0 + j - PAD;
            float v = 0.0f;
            if (gl >= 0 && gl < L) v = yprev[(size_t)ci * STRIDE_C + gl];
            ps[idx] = v;
        }
        #pragma unroll 1
        for (int idx = tid; idx < F4_PER_CHUNK; idx += NTH) {
            int co = idx / (CI_CHUNK * 3);
            int r  = idx % (CI_CHUNK * 3);
            *(float4*)&ws[co * WS_STRIDE + r * 4] = wsrc[(size_t)co * (C_ * 3) + r];
        }
    }
    __syncthreads();

    // lane mapping: lg = l group (8 x 4l = 32 l), cog = co (16)
    const int lg   = tid & 7;
    const int cog  = tid >> 3;
    const int lloc = lg * 4;

    float acc[4] = {0.f, 0.f, 0.f, 0.f};

    #pragma unroll 1
    for (int cb = 0; cb < NCHUNK; cb++) {
        const float* wsb = ws + (cb & 1) * WBUF;

        // prefetch next weight chunk into the other buffer (overlaps compute)
        if (cb + 1 < NCHUNK) {
            float* wsn = ws + ((cb + 1) & 1) * WBUF;
            const float4* src = wsrc + (cb + 1) * (CI_CHUNK * 3);
            #pragma unroll 1
            for (int idx = tid; idx < F4_PER_CHUNK; idx += NTH) {
                int co = idx / (CI_CHUNK * 3);
                int r  = idx % (CI_CHUNK * 3);
                *(float4*)&wsn[co * WS_STRIDE + r * 4] = src[(size_t)co * (C_ * 3) + r];
            }
        }

        const float* psbase = ps + cb * CI_CHUNK * (TL + 8) + lloc;
        const float* wbase  = wsb + cog * WS_STRIDE;

        #pragma unroll 4
        for (int ci = 0; ci < CI_CHUNK; ci++) {
            float4 p0 = *(const float4*)(psbase + ci * (TL + 8) + 0);
            float4 p1 = *(const float4*)(psbase + ci * (TL + 8) + 4);
            float4 p2 = *(const float4*)(psbase + ci * (TL + 8) + 8);
            float pv[12] = {p0.x,p0.y,p0.z,p0.w, p1.x,p1.y,p1.z,p1.w, p2.x,p2.y,p2.z,p2.w};

            float4 wa = *(const float4*)(wbase + ci * 12 + 0);
            float4 wb = *(const float4*)(wbase + ci * 12 + 4);
            float4 wc = *(const float4*)(wbase + ci * 12 + 8);
            float wr[9] = {wa.x,wa.y,wa.z,wa.w, wb.x,wb.y,wb.z,wb.w, wc.x};

            #pragma unroll
            for (int k = 0; k < KS; k++) {
                acc[0] = fmaf(wr[k], pv[0 + k], acc[0]);
                acc[1] = fmaf(wr[k], pv[1 + k], acc[1]);
                acc[2] = fmaf(wr[k], pv[2 + k], acc[2]);
                acc[3] = fmaf(wr[k], pv[3 + k], acc[3]);
            }
        }
        __syncthreads();
    }

    // ---- epilogue: y_cur += relu(acc), vector RMW ----
    float* yo = y + bbase + (size_t)(co0 + cog) * STRIDE_C + base_cur + l0 + lloc;
    float4 o = *(float4*)yo;
    o.x += fmaxf(acc[0], 0.f);
    o.y += fmaxf(acc[1], 0.f);
    o.z += fmaxf(acc[2], 0.f);
    o.w += fmaxf(acc[3], 0.f);
    *(float4*)yo = o;
}

extern "C" void kernel_launch(void* const* d_in, const int* in_sizes, int n_in,
                              void* d_out, int out_size)
{
    const float* x    = (const float*)d_in[0];
    const float* w_ud = (const float*)d_in[1];
    const float* w_du = (const float*)d_in[2];
    const float* w_lr = (const float*)d_in[3];
    const float* w_rl = (const float*)d_in[4];
    float* y = (float*)d_out;

    float* yt;  cudaGetSymbolAddress((void**)&yt, g_yt);
    float* wp;  cudaGetSymbolAddress((void**)&wp, g_wpad);

    const int SMEM = (C_ * (32 + 8) + 2 * WBUF) * 4;   // 70144 B
    cudaFuncSetAttribute(scnn_step<32>, cudaFuncAttributeMaxDynamicSharedMemorySize, SMEM);

    pad_weights<<<(4 * C_ * C_ + 127) / 128, 128>>>(w_ud, w_du, w_lr, w_rl);
    cudaMemcpyAsync(y, x, (size_t)out_size * sizeof(float), cudaMemcpyDeviceToDevice);

    const int WOFF = C_ * C_ * 12;

    // vertical passes on y: scan H, conv along W (L=256). grid = 8 x 8 x 8 = 512 blocks
    dim3 gridV(W_ / 32, C_ / TCO, B_);
    for (int h = 1; h < H_; h++)
        scnn_step<32><<<gridV, NTH, SMEM>>>(y, wp + 0 * WOFF, h * W_, (h - 1) * W_, W_);
    for (int h = H_ - 2; h >= 0; h--)
        scnn_step<32><<<gridV, NTH, SMEM>>>(y, wp + 1 * WOFF, h * W_, (h + 1) * W_, W_);

    // transpose y[B,C,H,W] -> yt[B,C,W,H]
    {
        dim3 g(W_ / 32, H_ / 32, B_ * C_);
        transpose_planes<<<g, dim3(32, 8)>>>(y, yt, H_, W_);
    }

    // horizontal passes on yt: scan W, conv along H (contiguous, L=128). grid = 4 x 8 x 8
    dim3 gridH(H_ / 32, C_ / TCO, B_);
    for (int wi = 1; wi < W_; wi++)
        scnn_step<32><<<gridH, NTH, SMEM>>>(yt, wp + 2 * WOFF, wi * H_, (wi - 1) * H_, H_);
    for (int wi = W_ - 2; wi >= 0; wi--)
        scnn_step<32><<<gridH, NTH, SMEM>>>(yt, wp + 3 * WOFF, wi * H_, (wi + 1) * H_, H_);

    // transpose back yt[B,C,W,H] -> y[B,C,H,W]
    {
        dim3 g(H_ / 32, W_ / 32, B_ * C_);
        transpose_planes<<<g, dim3(32, 8)>>>(yt, y, W_, H_);
    }
}

// round 5
// speedup vs baseline: 3.5232x; 1.5745x over previous
#include <cuda_runtime.h>

#define C_   128
#define H_   128
#define W_   256
#define B_   8
#define KS   9
#define PAD  4
#define TCO  16
#define CI_CHUNK 32
#define WSS  (CI_CHUNK*12 + 4)     // 388 floats/co row; 388%32=4 -> conflict-free
#define STRIDE_C (H_*W_)

__device__ float g_yt[(size_t)B_ * C_ * H_ * W_];     // transposed tensor scratch
__device__ float g_wpad[4 * C_ * C_ * 12];            // padded weights

// ---------------- weight padding: w[co][ci][9] -> wpad[p][co][ci][12] ----------------
__global__ void pad_weights(const float* __restrict__ w0, const float* __restrict__ w1,
                            const float* __restrict__ w2, const float* __restrict__ w3)
{
    int row = blockIdx.x * blockDim.x + threadIdx.x;
    if (row >= 4 * C_ * C_) return;
    int p  = row / (C_ * C_);
    int rc = row % (C_ * C_);
    const float* src = (p == 0 ? w0 : p == 1 ? w1 : p == 2 ? w2 : w3) + rc * KS;
    float* dst = g_wpad + (size_t)row * 12;
    #pragma unroll
    for (int k = 0; k < 9; k++) dst[k] = src[k];
    dst[9] = 0.f; dst[10] = 0.f; dst[11] = 0.f;
}

// ---------------- 32x32 tiled transpose of [R x Ccols] planes ----------------
__global__ void transpose_planes(const float* __restrict__ src, float* __restrict__ dst,
                                 int R, int Ccols)
{
    __shared__ float t[32][33];
    size_t plane = (size_t)blockIdx.z * R * Ccols;
    int x  = blockIdx.x * 32 + threadIdx.x;
    int y0 = blockIdx.y * 32 + threadIdx.y;
    #pragma unroll
    for (int j = 0; j < 32; j += 8)
        t[threadIdx.y + j][threadIdx.x] = src[plane + (size_t)(y0 + j) * Ccols + x];
    __syncthreads();
    int xo = blockIdx.y * 32 + threadIdx.x;
    int yo = blockIdx.x * 32 + threadIdx.y;
    #pragma unroll
    for (int j = 0; j < 32; j += 8)
        dst[plane + (size_t)(yo + j) * R + xo] = t[threadIdx.x][threadIdx.y + j];
}

// ---------------- one scan step: y[cur] += relu(conv1d(y[prev])) ----------------
// micro-tile: 1 co x 4 l per thread. NTH = 16 co * (TL/4) lgroups.
template<int TL>
__global__ __launch_bounds__((TL/4)*TCO) void scnn_step(
    float* __restrict__ y, const float* __restrict__ wp,
    int base_cur, int base_prev, int L)
{
    constexpr int NTH    = (TL/4) * TCO;
    constexpr int ROWLEN = TL + 2*PAD;
    constexpr int LGN    = TL/4;          // l-groups (8 or 4), power of 2

    extern __shared__ float smem[];
    float* ps = smem;                     // [C_][ROWLEN]
    float* ws = smem + C_ * ROWLEN;       // [TCO][WSS]

    const int b   = blockIdx.z;
    const int co0 = blockIdx.y * TCO;
    const int l0  = blockIdx.x * TL;
    const int tid = threadIdx.x;
    const size_t bbase = (size_t)b * C_ * STRIDE_C;

    // ---- stage prev row: aligned main part (pure shifts) ----
    {
        const float* yprevb = y + bbase + base_prev;
        constexpr int JV = TL / 4;                       // float4 per row main
        #pragma unroll 1
        for (int idx = tid; idx < C_ * JV; idx += NTH) {
            int ci = idx / JV;                           // JV power of 2 -> shift
            int jv = idx & (JV - 1);
            float4 v = *(const float4*)(yprevb + (size_t)ci * STRIDE_C + l0 + jv * 4);
            *(float4*)&ps[ci * ROWLEN + PAD + jv * 4] = v;
        }
        // halo: 4 left + 4 right per ci, bounds-checked
        #pragma unroll 1
        for (int idx = tid; idx < C_ * 8; idx += NTH) {
            int ci = idx >> 3;
            int j  = idx & 7;
            int gl, so;
            if (j < 4) { gl = l0 - 4 + j;      so = j; }
            else       { gl = l0 + TL + j - 4; so = PAD + TL + j - 4; }
            float v = 0.0f;
            if (gl >= 0 && gl < L) v = yprevb[(size_t)ci * STRIDE_C + gl];
            ps[ci * ROWLEN + so] = v;
        }
    }

    const int lg  = tid & (LGN - 1);
    const int cog = tid >> ((TL == 32) ? 3 : 2);   // tid / LGN
    const int lloc = lg * 4;

    float acc[4] = {0.f, 0.f, 0.f, 0.f};

    const float4* wsrc = (const float4*)(wp + (size_t)co0 * (C_ * 12));
    constexpr int WTH = NTH / TCO;                 // threads per co for staging (8 or 4)
    constexpr int WIT = (CI_CHUNK * 3) / WTH;      // float4 iters per thread
    const int wco = tid / WTH;                     // stage-co for this thread
    const int wr0 = tid & (WTH - 1);

    #pragma unroll 1
    for (int cb = 0; cb < C_ / CI_CHUNK; cb++) {
        __syncthreads();
        // stage weight chunk [TCO][CI_CHUNK*12] via float4, shift-only indexing
        {
            const float4* src = wsrc + (size_t)wco * (C_ * 3) + cb * (CI_CHUNK * 3);
            float4* dst = (float4*)&ws[wco * WSS];
            #pragma unroll
            for (int i = 0; i < WIT; i++)
                dst[wr0 + i * WTH] = src[wr0 + i * WTH];
        }
        __syncthreads();

        const float* psrow = ps + (cb * CI_CHUNK) * ROWLEN + lloc;
        const float* wrow  = ws + cog * WSS;

        // register-pipelined: load ci+1 while FMAing ci
        float4 pa = *(const float4*)(psrow + 0);
        float4 pb = *(const float4*)(psrow + 4);
        float4 pc = *(const float4*)(psrow + 8);
        float4 wa = *(const float4*)(wrow + 0);
        float4 wb = *(const float4*)(wrow + 4);
        float4 wc = *(const float4*)(wrow + 8);

        #pragma unroll
        for (int ci = 0; ci < CI_CHUNK; ci++) {
            float4 npa, npb, npc, nwa, nwb, nwc;
            if (ci + 1 < CI_CHUNK) {
                const float* pn = psrow + (ci + 1) * ROWLEN;
                const float* wn = wrow  + (ci + 1) * 12;
                npa = *(const float4*)(pn + 0);
                npb = *(const float4*)(pn + 4);
                npc = *(const float4*)(pn + 8);
                nwa = *(const float4*)(wn + 0);
                nwb = *(const float4*)(wn + 4);
                nwc = *(const float4*)(wn + 8);
            }

            const float pv[12] = {pa.x,pa.y,pa.z,pa.w, pb.x,pb.y,pb.z,pb.w,
                                  pc.x,pc.y,pc.z,pc.w};
            const float wv[9]  = {wa.x,wa.y,wa.z,wa.w, wb.x,wb.y,wb.z,wb.w, wc.x};

            #pragma unroll
            for (int k = 0; k < KS; k++) {
                acc[0] = fmaf(wv[k], pv[0 + k], acc[0]);
                acc[1] = fmaf(wv[k], pv[1 + k], acc[1]);
                acc[2] = fmaf(wv[k], pv[2 + k], acc[2]);
                acc[3] = fmaf(wv[k], pv[3 + k], acc[3]);
            }

            if (ci + 1 < CI_CHUNK) {
                pa = npa; pb = npb; pc = npc;
                wa = nwa; wb = nwb; wc = nwc;
            }
        }
    }

    // ---- epilogue: y_cur += relu(acc), float4 RMW ----
    float* yo = y + bbase + (size_t)(co0 + cog) * STRIDE_C + base_cur + l0 + lloc;
    float4 o = *(float4*)yo;
    o.x += fmaxf(acc[0], 0.f);
    o.y += fmaxf(acc[1], 0.f);
    o.z += fmaxf(acc[2], 0.f);
    o.w += fmaxf(acc[3], 0.f);
    *(float4*)yo = o;
}

extern "C" void kernel_launch(void* const* d_in, const int* in_sizes, int n_in,
                              void* d_out, int out_size)
{
    const float* x    = (const float*)d_in[0];
    const float* w_ud = (const float*)d_in[1];
    const float* w_du = (const float*)d_in[2];
    const float* w_lr = (const float*)d_in[3];
    const float* w_rl = (const float*)d_in[4];
    float* y = (float*)d_out;

    float* yt;  cudaGetSymbolAddress((void**)&yt, g_yt);
    float* wp;  cudaGetSymbolAddress((void**)&wp, g_wpad);

    const int SMEM_V = (C_ * (32 + 8) + TCO * WSS) * 4;   // 45312 B
    const int SMEM_H = (C_ * (16 + 8) + TCO * WSS) * 4;   // 37120 B
    cudaFuncSetAttribute(scnn_step<32>, cudaFuncAttributeMaxDynamicSharedMemorySize, SMEM_V);
    cudaFuncSetAttribute(scnn_step<16>, cudaFuncAttributeMaxDynamicSharedMemorySize, SMEM_H);

    pad_weights<<<(4 * C_ * C_ + 127) / 128, 128>>>(w_ud, w_du, w_lr, w_rl);
    cudaMemcpyAsync(y, x, (size_t)out_size * sizeof(float), cudaMemcpyDeviceToDevice);

    const int WOFF = C_ * C_ * 12;

    // vertical passes: scan H, conv along W. grid 8x8x8=512 blocks x 4 warps
    dim3 gridV(W_ / 32, C_ / TCO, B_);
    for (int h = 1; h < H_; h++)
        scnn_step<32><<<gridV, 128, SMEM_V>>>(y, wp + 0 * WOFF, h * W_, (h - 1) * W_, W_);
    for (int h = H_ - 2; h >= 0; h--)
        scnn_step<32><<<gridV, 128, SMEM_V>>>(y, wp + 1 * WOFF, h * W_, (h + 1) * W_, W_);

    // transpose y[B,C,H,W] -> yt[B,C,W,H]
    {
        dim3 g(W_ / 32, H_ / 32, B_ * C_);
        transpose_planes<<<g, dim3(32, 8)>>>(y, yt, H_, W_);
    }

    // horizontal passes on yt: scan W, conv along H. grid 8x8x8=512 blocks x 2 warps
    dim3 gridH(H_ / 16, C_ / TCO, B_);
    for (int wi = 1; wi < W_; wi++)
        scnn_step<16><<<gridH, 64, SMEM_H>>>(yt, wp + 2 * WOFF, wi * H_, (wi - 1) * H_, H_);
    for (int wi = W_ - 2; wi >= 0; wi--)
        scnn_step<16><<<gridH, 64, SMEM_H>>>(yt, wp + 3 * WOFF, wi * H_, (wi + 1) * H_, H_);

    // transpose back yt[B,C,W,H] -> y[B,C,H,W]
    {
        dim3 g(H_ / 32, W_ / 32, B_ * C_);
        transpose_planes<<<g, dim3(32, 8)>>>(yt, y, W_, H_);
    }
}